// round 5
// baseline (speedup 1.0000x reference)
#include <cuda_runtime.h>
#include <math.h>

#define NN   1024
#define DNF  128
#define G3   384
#define NB   128
#define NTHR 256
#define TLD  68

// ---------------- device scratch ----------------
__device__ float g_er  [NN * DNF];
__device__ float g_cei [NN * G3];
__device__ float g_sh  [NN * DNF];
__device__ float g_gi  [NN * G3];
__device__ float g_gh  [NN * G3];
__device__ float g_h   [NN * DNF];
__device__ float g_wim [G3 * DNF];     // w_ih @ w_msg_h   (fp32)
__device__ float g_wie [G3 * DNF];     // w_ih @ w_msg_e   (fp32)
__device__ float g_bvec[G3];           // w_ih @ b_msg
__device__ float g_ro  [2 * NN * DNF];
__device__ int   g_nzi [NN * NN];
__device__ float g_nzv [NN * NN];
__device__ int   g_nzc [NN];
__device__ float g_part[NB * DNF];
__device__ int   g_bar_in [32];
__device__ int   g_bar_out[32];

// ---------------- global barrier (self-resetting per use) ----------------
__device__ __forceinline__ void gbar(int k) {
    __syncthreads();
    if (threadIdx.x == 0) {
        __threadfence();
        atomicAdd(&g_bar_in[k], 1);
        while (((volatile int*)g_bar_in)[k] < NB) { }
        int o = atomicAdd(&g_bar_out[k], 1);
        if (o == NB - 1) { g_bar_in[k] = 0; g_bar_out[k] = 0; __threadfence(); }
    }
    __syncthreads();
    __threadfence();
}

__device__ __forceinline__ float to_tf32(float x) {
    float r;
    asm("cvt.rna.tf32.f32 %0, %1;" : "=f"(r) : "f"(x));
    return r;
}
__device__ __forceinline__ float sigf(float x) { return 1.0f / (1.0f + expf(-x)); }

// ---------------------------------------------------------------------------
// TF32 MMA tile: C[64 x 32*NFRAG] at (bm, bn).
// C = sum_p A_p[.,128] @ W[:, p*128:+128]^T (+bias) (+D)
// 256 threads = 8 warps (2 m x 4 n). Same fragment math as validated round-4.
// ---------------------------------------------------------------------------
template<int NFRAG>
__device__ __forceinline__ void gemm_tile(
    const float* __restrict__ A0, const float* __restrict__ A1, int lda,
    const float* __restrict__ W, int ldw,
    const float* __restrict__ D, const float* __restrict__ bias,
    float* __restrict__ C, int ldc, int nparts,
    int bm, int bn, float* As, float* Ws)
{
    const int tid  = threadIdx.x;
    const int lane = tid & 31, wrp = tid >> 5;
    const int wm   = wrp >> 2, wn = wrp & 3;
    const int q    = lane >> 2, r = lane & 3;

    float acc[2][NFRAG][4];
#pragma unroll
    for (int s = 0; s < 2; s++)
#pragma unroll
        for (int j = 0; j < NFRAG; j++)
#pragma unroll
            for (int c = 0; c < 4; c++) acc[s][j][c] = 0.f;

    for (int p = 0; p < nparts; p++) {
        const float* Ap = p ? A1 : A0;
        const float* Wp = W + p * 128;
#pragma unroll
        for (int kt = 0; kt < 2; kt++) {
#pragma unroll
            for (int u = 0; u < 4; u++) {                 // A: 64 x 64
                int idx = tid + u * NTHR;
                int row = idx >> 4, kq = idx & 15;
                float4 v = *(const float4*)(Ap + (size_t)(bm + row) * lda
                                            + kt * 64 + kq * 4);
                float* dd = As + row * TLD + kq * 4;
                dd[0] = to_tf32(v.x); dd[1] = to_tf32(v.y);
                dd[2] = to_tf32(v.z); dd[3] = to_tf32(v.w);
            }
#pragma unroll
            for (int u = 0; u < NFRAG * 2; u++) {         // W: 32*NFRAG x 64
                int idx = tid + u * NTHR;
                int row = idx >> 4, kq = idx & 15;
                float4 v = *(const float4*)(Wp + (size_t)(bn + row) * ldw
                                            + kt * 64 + kq * 4);
                float* dd = Ws + row * TLD + kq * 4;
                dd[0] = to_tf32(v.x); dd[1] = to_tf32(v.y);
                dd[2] = to_tf32(v.z); dd[3] = to_tf32(v.w);
            }
            __syncthreads();
#pragma unroll
            for (int k8 = 0; k8 < 8; k8++) {
                const int ko = k8 * 8;
                unsigned a[2][4];
#pragma unroll
                for (int s = 0; s < 2; s++) {
                    int ar = wm * 32 + s * 16 + q;
                    a[s][0] = __float_as_uint(As[(ar    ) * TLD + ko + r    ]);
                    a[s][1] = __float_as_uint(As[(ar + 8) * TLD + ko + r    ]);
                    a[s][2] = __float_as_uint(As[(ar    ) * TLD + ko + r + 4]);
                    a[s][3] = __float_as_uint(As[(ar + 8) * TLD + ko + r + 4]);
                }
                unsigned b[NFRAG][2];
#pragma unroll
                for (int j = 0; j < NFRAG; j++) {
                    int nr = wn * (NFRAG * 8) + j * 8 + q;
                    b[j][0] = __float_as_uint(Ws[nr * TLD + ko + r    ]);
                    b[j][1] = __float_as_uint(Ws[nr * TLD + ko + r + 4]);
                }
#pragma unroll
                for (int s = 0; s < 2; s++)
#pragma unroll
                    for (int j = 0; j < NFRAG; j++)
                        asm volatile(
                            "mma.sync.aligned.m16n8k8.row.col.f32.tf32.tf32.f32 "
                            "{%0,%1,%2,%3}, {%4,%5,%6,%7}, {%8,%9}, {%0,%1,%2,%3};"
                            : "+f"(acc[s][j][0]), "+f"(acc[s][j][1]),
                              "+f"(acc[s][j][2]), "+f"(acc[s][j][3])
                            : "r"(a[s][0]), "r"(a[s][1]), "r"(a[s][2]), "r"(a[s][3]),
                              "r"(b[j][0]), "r"(b[j][1]));
            }
            __syncthreads();
        }
    }
#pragma unroll
    for (int s = 0; s < 2; s++) {
        int row0 = bm + wm * 32 + s * 16 + q;
#pragma unroll
        for (int j = 0; j < NFRAG; j++) {
            int col = bn + wn * (NFRAG * 8) + j * 8 + 2 * r;
            float v0 = acc[s][j][0], v1 = acc[s][j][1];
            float v2 = acc[s][j][2], v3 = acc[s][j][3];
            if (bias) {
                float b0 = bias[col], b1 = bias[col + 1];
                v0 += b0; v1 += b1; v2 += b0; v3 += b1;
            }
            if (D) {
                v0 += D[(size_t)row0 * ldc + col];
                v1 += D[(size_t)row0 * ldc + col + 1];
                v2 += D[(size_t)(row0 + 8) * ldc + col];
                v3 += D[(size_t)(row0 + 8) * ldc + col + 1];
            }
            *(float2*)(C + (size_t)row0 * ldc + col)       = make_float2(v0, v1);
            *(float2*)(C + (size_t)(row0 + 8) * ldc + col) = make_float2(v2, v3);
        }
    }
}

// nz-list broadcast: first 64 entries register-cached per warp, rest from global
__device__ __forceinline__ void get_nz(int k, int i0, int i1, float v0, float v1,
                                       const int* gip, const float* gvp,
                                       int& j, float& v) {
    if (k < 32)      { j = __shfl_sync(0xffffffffu, i0, k);      v = __shfl_sync(0xffffffffu, v0, k); }
    else if (k < 64) { j = __shfl_sync(0xffffffffu, i1, k - 32); v = __shfl_sync(0xffffffffu, v1, k - 32); }
    else             { j = gip[k]; v = gvp[k]; }
}

// ---------------------------------------------------------------------------
__global__ void __launch_bounds__(NTHR, 1)
k_mono(const float* __restrict__ h_in,  const float* __restrict__ e,
       const float* __restrict__ adj,   const float* __restrict__ edge,
       const float* __restrict__ w_msg_h, const float* __restrict__ w_msg_e,
       const float* __restrict__ b_msg,
       const float* __restrict__ w_ih,  const float* __restrict__ w_hh,
       const float* __restrict__ b_ih,  const float* __restrict__ b_hh,
       const float* __restrict__ w_gate, const float* __restrict__ b_gate,
       const float* __restrict__ w_out, const float* __restrict__ b_out,
       const float* __restrict__ w_embed, const float* __restrict__ w_fc,
       const float* __restrict__ b_fc,  float* __restrict__ out)
{
    __shared__ __align__(16) float s_smem[10880];   // 43.5 KB union
    float* As = s_smem;
    float* Ws = s_smem + 4352;

    const int bid  = blockIdx.x;
    const int tid  = threadIdx.x;
    const int lane = tid & 31;
    const int wid  = tid >> 5;

    // ================= P0: adjacency compaction + e-reduce (warp/row) ======
    {
        const int row = bid * 8 + wid;
        const float* arow = adj + (size_t)row * NN;
        const unsigned lm = (1u << lane) - 1u;
        int off = 0;
        for (int c = 0; c < 32; c++) {
            float v = arow[c * 32 + lane];
            unsigned m = __ballot_sync(0xffffffffu, v != 0.0f);
            if (v != 0.0f) {
                int p = off + __popc(m & lm);
                g_nzi[(size_t)row * NN + p] = c * 32 + lane;
                g_nzv[(size_t)row * NN + p] = v;
            }
            off += __popc(m);
        }
        if (lane == 0) g_nzc[row] = off;
        __syncwarp();

        const int cnt = off;
        const int*   gip = g_nzi + (size_t)row * NN;
        const float* gvp = g_nzv + (size_t)row * NN;
        int i0 = 0, i1 = 0; float v0 = 0.f, v1 = 0.f;
        if (lane < cnt)      { i0 = gip[lane];      v0 = gvp[lane]; }
        if (32 + lane < cnt) { i1 = gip[32 + lane]; v1 = gvp[32 + lane]; }

        const float* eb = e + (size_t)row * NN * DNF;
        float4 acc = make_float4(0.f, 0.f, 0.f, 0.f);
        int k = 0;
        for (; k + 4 <= cnt; k += 4) {
            int j0, j1, j2, j3; float w0, w1, w2, w3;
            get_nz(k,     i0, i1, v0, v1, gip, gvp, j0, w0);
            get_nz(k + 1, i0, i1, v0, v1, gip, gvp, j1, w1);
            get_nz(k + 2, i0, i1, v0, v1, gip, gvp, j2, w2);
            get_nz(k + 3, i0, i1, v0, v1, gip, gvp, j3, w3);
            float4 e0 = *(const float4*)(eb + (size_t)j0 * DNF + lane * 4);
            float4 e1 = *(const float4*)(eb + (size_t)j1 * DNF + lane * 4);
            float4 e2 = *(const float4*)(eb + (size_t)j2 * DNF + lane * 4);
            float4 e3 = *(const float4*)(eb + (size_t)j3 * DNF + lane * 4);
            acc.x += w0*e0.x + w1*e1.x + w2*e2.x + w3*e3.x;
            acc.y += w0*e0.y + w1*e1.y + w2*e2.y + w3*e3.y;
            acc.z += w0*e0.z + w1*e1.z + w2*e2.z + w3*e3.z;
            acc.w += w0*e0.w + w1*e1.w + w2*e2.w + w3*e3.w;
        }
        for (; k < cnt; k++) {
            int j; float w;
            get_nz(k, i0, i1, v0, v1, gip, gvp, j, w);
            float4 ev = *(const float4*)(eb + (size_t)j * DNF + lane * 4);
            acc.x += w*ev.x; acc.y += w*ev.y; acc.z += w*ev.z; acc.w += w*ev.w;
        }
        *(float4*)(g_er + (size_t)row * DNF + lane * 4) = acc;
    }

    // ---- P0b: wim = w_ih @ w_msg_h, wie = w_ih @ w_msg_e  (fp32, 6 rows/blk)
    {
        const int d = tid & 127;
#pragma unroll
        for (int pr = 0; pr < 3; pr++) {
            int rr = bid * 6 + pr * 2 + (tid >> 7);     // 0..767
            const float* wrow; const float* B; float* o;
            if (rr < G3) { wrow = w_ih + (size_t)rr * DNF;        B = w_msg_h; o = g_wim + (size_t)rr * DNF; }
            else         { wrow = w_ih + (size_t)(rr - G3) * DNF; B = w_msg_e; o = g_wie + (size_t)(rr - G3) * DNF; }
            float acc = 0.f;
#pragma unroll 4
            for (int k = 0; k < DNF; k++) acc += wrow[k] * B[k * DNF + d];
            o[d] = acc;
        }
        // bvec = w_ih @ b_msg
        if (bid < 3 && tid < 128) {
            int n = bid * 128 + tid;
            float acc = 0.f;
            const float* wr = w_ih + (size_t)n * DNF;
            for (int k = 0; k < DNF; k++) acc += wr[k] * b_msg[k];
            g_bvec[n] = acc;
        }
    }
    gbar(0);

    // ================= P1: cei = er @ wie^T + bvec  (64 tiles) ==============
    if (bid < 64) {
        int tm = bid & 15, tn = bid >> 4;
        gemm_tile<3>(g_er, nullptr, DNF, g_wie, DNF, nullptr, g_bvec,
                     g_cei, G3, 1, tm * 64, tn * 96, As, Ws);
    }
    gbar(1);

    // ================= layers ==============================================
    int bar = 2;
    const float* hcur = h_in;
    for (int l = 0; l < 4; l++) {
        // ---- spmv: sh = S . hcur (warp/row)
        {
            const int row = bid * 8 + wid;
            const int cnt = g_nzc[row];
            const int*   gip = g_nzi + (size_t)row * NN;
            const float* gvp = g_nzv + (size_t)row * NN;
            int i0 = 0, i1 = 0; float v0 = 0.f, v1 = 0.f;
            if (lane < cnt)      { i0 = gip[lane];      v0 = gvp[lane]; }
            if (32 + lane < cnt) { i1 = gip[32 + lane]; v1 = gvp[32 + lane]; }

            float4 acc = make_float4(0.f, 0.f, 0.f, 0.f);
            int k = 0;
            for (; k + 4 <= cnt; k += 4) {
                int j0, j1, j2, j3; float w0, w1, w2, w3;
                get_nz(k,     i0, i1, v0, v1, gip, gvp, j0, w0);
                get_nz(k + 1, i0, i1, v0, v1, gip, gvp, j1, w1);
                get_nz(k + 2, i0, i1, v0, v1, gip, gvp, j2, w2);
                get_nz(k + 3, i0, i1, v0, v1, gip, gvp, j3, w3);
                float4 h0 = *(const float4*)(hcur + (size_t)j0 * DNF + lane * 4);
                float4 h1 = *(const float4*)(hcur + (size_t)j1 * DNF + lane * 4);
                float4 h2 = *(const float4*)(hcur + (size_t)j2 * DNF + lane * 4);
                float4 h3 = *(const float4*)(hcur + (size_t)j3 * DNF + lane * 4);
                acc.x += w0*h0.x + w1*h1.x + w2*h2.x + w3*h3.x;
                acc.y += w0*h0.y + w1*h1.y + w2*h2.y + w3*h3.y;
                acc.z += w0*h0.z + w1*h1.z + w2*h2.z + w3*h3.z;
                acc.w += w0*h0.w + w1*h1.w + w2*h2.w + w3*h3.w;
            }
            for (; k < cnt; k++) {
                int j; float w;
                get_nz(k, i0, i1, v0, v1, gip, gvp, j, w);
                float4 hv = *(const float4*)(hcur + (size_t)j * DNF + lane * 4);
                acc.x += w*hv.x; acc.y += w*hv.y; acc.z += w*hv.z; acc.w += w*hv.w;
            }
            *(float4*)(g_sh + (size_t)row * DNF + lane * 4) = acc;
        }
        gbar(bar++);

        // ---- gi = sh@wim^T + cei ; gh = hcur@w_hh^T  (128 tiles, 1/block)
        {
            int which = bid >> 6, tt = bid & 63;
            int tm = tt & 15, tn = tt >> 4;
            if (which == 0)
                gemm_tile<3>(g_sh, nullptr, DNF, g_wim, DNF, g_cei, nullptr,
                             g_gi, G3, 1, tm * 64, tn * 96, As, Ws);
            else
                gemm_tile<3>(hcur, nullptr, DNF, w_hh, DNF, nullptr, nullptr,
                             g_gh, G3, 1, tm * 64, tn * 96, As, Ws);
        }
        gbar(bar++);

        // ---- GRU
        for (int jj = tid; jj < 1024; jj += NTHR) {
            int gid = bid * 1024 + jj;
            int i = gid >> 7, d = gid & 127;
            const float* gi = g_gi + (size_t)i * G3;
            const float* gh = g_gh + (size_t)i * G3;
            float rr = sigf(gi[d]       + b_ih[d]       + gh[d]       + b_hh[d]);
            float zz = sigf(gi[128 + d] + b_ih[128 + d] + gh[128 + d] + b_hh[128 + d]);
            float nn = tanhf(gi[256 + d] + b_ih[256 + d]
                             + rr * (gh[256 + d] + b_hh[256 + d]));
            g_h[gid] = (1.0f - zz) * nn + zz * hcur[gid];
        }
        gbar(bar++);
        hcur = g_h;
    }

    // ================= readout GEMMs (64 tiles) ============================
    if (bid < 64) {
        int which = bid >> 5, tt = bid & 31;
        int tm = tt & 15, tn = tt >> 4;
        if (which == 0)
            gemm_tile<2>(g_h, h_in, DNF, w_gate, 256, nullptr, b_gate,
                         g_ro, DNF, 2, tm * 64, tn * 64, As, Ws);
        else
            gemm_tile<2>(g_h, h_in, DNF, w_out, 256, nullptr, b_out,
                         g_ro + (size_t)NN * DNF, DNF, 2, tm * 64, tn * 64, As, Ws);
    }
    gbar(bar++);

    // ================= readout partials (8 rows/block) =====================
    {
        int d = tid & 127, half = tid >> 7;
        float a = 0.f;
#pragma unroll
        for (int rr = 0; rr < 4; rr++) {
            int i = bid * 8 + half * 4 + rr;
            a += sigf(g_ro[(size_t)i * DNF + d])
               * tanhf(g_ro[(size_t)(NN + i) * DNF + d]);
        }
        s_smem[tid] = a;
        __syncthreads();
        if (tid < 128) g_part[bid * DNF + tid] = s_smem[tid] + s_smem[tid + 128];
    }
    gbar(bar++);

    // ================= final (block 0) =====================================
    if (bid == 0) {
        if (tid < 128) {
            int d = tid;
            float gv = 0.f;
            for (int b = 0; b < NB; b++) gv += g_part[b * DNF + d];
            s_smem[d] = gv;
            float ee = 0.f;
#pragma unroll
            for (int f = 0; f < 5; f++) ee += w_embed[d * 5 + f] * edge[f];
            s_smem[128 + d] = ee;
        }
        __syncthreads();
        if (tid < 128) {
            int d = tid;
            float acc = b_fc[d];
            const float* wr = w_fc + (size_t)d * 256;
            for (int k = 0; k < 128; k++) acc += wr[k] * s_smem[k];
            for (int k = 0; k < 128; k++) acc += wr[128 + k] * s_smem[128 + k];
            out[d] = acc;
        }
    }
}

// ---------------------------------------------------------------------------
extern "C" void kernel_launch(void* const* d_in, const int* in_sizes, int n_in,
                              void* d_out, int out_size) {
    const float* h_in    = (const float*)d_in[0];
    const float* e       = (const float*)d_in[1];
    const float* adj     = (const float*)d_in[2];
    const float* edge    = (const float*)d_in[3];
    const float* w_msg_h = (const float*)d_in[4];
    const float* w_msg_e = (const float*)d_in[5];
    const float* b_msg   = (const float*)d_in[6];
    const float* w_ih    = (const float*)d_in[7];
    const float* w_hh    = (const float*)d_in[8];
    const float* b_ih    = (const float*)d_in[9];
    const float* b_hh    = (const float*)d_in[10];
    const float* w_gate  = (const float*)d_in[11];
    const float* b_gate  = (const float*)d_in[12];
    const float* w_out   = (const float*)d_in[13];
    const float* b_out   = (const float*)d_in[14];
    const float* w_embed = (const float*)d_in[15];
    const float* w_fc    = (const float*)d_in[16];
    const float* b_fc    = (const float*)d_in[17];
    float* out = (float*)d_out;

    k_mono<<<NB, NTHR>>>(h_in, e, adj, edge, w_msg_h, w_msg_e, b_msg,
                         w_ih, w_hh, b_ih, b_hh, w_gate, b_gate, w_out, b_out,
                         w_embed, w_fc, b_fc, out);
}

// round 7
// speedup vs baseline: 1.1218x; 1.1218x over previous
#include <cuda_runtime.h>
#include <math.h>

#define NN   1024
#define DNF  128
#define G3   384
#define SLD  132     // A-tile smem stride: 128 k-floats + 4 pad
#define GA_LD 260
#define GB_LD 132

// ---------------- device scratch ----------------
__device__ float g_er  [NN * DNF];
__device__ float g_cei [NN * G3];      // er @ wie^T + bvec (layer-invariant)
__device__ float g_ha  [NN * DNF];
__device__ float g_hb  [NN * DNF];
__device__ float g_wimP[16 * 48 * 64]; // packed tf32 frags: (w_ih@w_msg_h), K=128,N=384
__device__ float g_wieP[16 * 48 * 64];
__device__ float g_whhP[16 * 48 * 64];
__device__ float g_wgP [32 * 16 * 64]; // w_gate, K=256, N=128
__device__ float g_woP [32 * 16 * 64];
__device__ float g_bvec[G3];
__device__ int   g_nzi [NN * NN];
__device__ float g_nzv [NN * NN];
__device__ int   g_nzc [NN];
__device__ float g_part[64 * DNF];
__device__ int   g_rc;

// ---------------- helpers ----------------
__device__ __forceinline__ float to_tf32(float x) {
    float r; asm("cvt.rna.tf32.f32 %0, %1;" : "=f"(r) : "f"(x)); return r;
}
__device__ __forceinline__ float sigf(float x) { return 1.0f / (1.0f + expf(-x)); }

__device__ __forceinline__ void mma_tf32(float* c, const unsigned* a,
                                         unsigned b0, unsigned b1) {
    asm volatile(
        "mma.sync.aligned.m16n8k8.row.col.f32.tf32.tf32.f32 "
        "{%0,%1,%2,%3}, {%4,%5,%6,%7}, {%8,%9}, {%0,%1,%2,%3};"
        : "+f"(c[0]), "+f"(c[1]), "+f"(c[2]), "+f"(c[3])
        : "r"(a[0]), "r"(a[1]), "r"(a[2]), "r"(a[3]), "r"(b0), "r"(b1));
}

// packed fragment index for W[N][K] (k-major rows): B-frag of (k8, n8),
// lane = q*4+r holds {W[n8*8+q][k8*8+r], W[n8*8+q][k8*8+r+4]}
__device__ __forceinline__ int pidx(int n, int k, int nfr) {
    int n8 = n >> 3, q = n & 7, k8 = k >> 3, kk = k & 7;
    int half = kk >> 2, r = kk & 3;
    return ((k8 * nfr + n8) * 32 + q * 4 + r) * 2 + half;
}

// nz-list broadcast: first 64 entries register-cached per warp
__device__ __forceinline__ void get_nz(int k, int i0, int i1, float v0, float v1,
                                       const int* gip, const float* gvp,
                                       int& j, float& v) {
    if (k < 32)      { j = __shfl_sync(0xffffffffu, i0, k);      v = __shfl_sync(0xffffffffu, v0, k); }
    else if (k < 64) { j = __shfl_sync(0xffffffffu, i1, k - 32); v = __shfl_sync(0xffffffffu, v1, k - 32); }
    else             { j = gip[k]; v = gvp[k]; }
}

// warp gather: acc4 = sum_k v_k * src[idx_k][lane*4..+4)
__device__ __forceinline__ float4 warp_gather(const float* __restrict__ src,
                                              const int* gip, const float* gvp,
                                              int cnt, int lane) {
    int i0 = 0, i1 = 0; float v0 = 0.f, v1 = 0.f;
    if (lane < cnt)      { i0 = gip[lane];      v0 = gvp[lane]; }
    if (32 + lane < cnt) { i1 = gip[32 + lane]; v1 = gvp[32 + lane]; }
    float4 acc = make_float4(0.f, 0.f, 0.f, 0.f);
    int k = 0;
    for (; k + 4 <= cnt; k += 4) {
        int j0, j1, j2, j3; float w0, w1, w2, w3;
        get_nz(k,     i0, i1, v0, v1, gip, gvp, j0, w0);
        get_nz(k + 1, i0, i1, v0, v1, gip, gvp, j1, w1);
        get_nz(k + 2, i0, i1, v0, v1, gip, gvp, j2, w2);
        get_nz(k + 3, i0, i1, v0, v1, gip, gvp, j3, w3);
        float4 a0 = *(const float4*)(src + (size_t)j0 * DNF + lane * 4);
        float4 a1 = *(const float4*)(src + (size_t)j1 * DNF + lane * 4);
        float4 a2 = *(const float4*)(src + (size_t)j2 * DNF + lane * 4);
        float4 a3 = *(const float4*)(src + (size_t)j3 * DNF + lane * 4);
        acc.x += w0*a0.x + w1*a1.x + w2*a2.x + w3*a3.x;
        acc.y += w0*a0.y + w1*a1.y + w2*a2.y + w3*a3.y;
        acc.z += w0*a0.z + w1*a1.z + w2*a2.z + w3*a3.z;
        acc.w += w0*a0.w + w1*a1.w + w2*a2.w + w3*a3.w;
    }
    for (; k < cnt; k++) {
        int j; float w;
        get_nz(k, i0, i1, v0, v1, gip, gvp, j, w);
        float4 av = *(const float4*)(src + (size_t)j * DNF + lane * 4);
        acc.x += w*av.x; acc.y += w*av.y; acc.z += w*av.z; acc.w += w*av.w;
    }
    return acc;
}

// ---------------------------------------------------------------------------
// k_setup: bid<1024 — adjacency compaction + er; bid>=1024 — weight
// products (wim, wie), packing (whh, wgate, wout), bvec.   256 threads.
// ---------------------------------------------------------------------------
__global__ void __launch_bounds__(256)
k_setup(const float* __restrict__ adj, const float* __restrict__ e,
        const float* __restrict__ w_msg_h, const float* __restrict__ w_msg_e,
        const float* __restrict__ w_ih, const float* __restrict__ b_msg,
        const float* __restrict__ w_hh, const float* __restrict__ w_gate,
        const float* __restrict__ w_out) {
    const int bid = blockIdx.x;
    const int tid = threadIdx.x;

    if (bid < NN) {
        // ---- adjacency compaction + e-reduce (row = bid) ----
        const int i    = bid;
        const int lane = tid & 31;
        const int w    = tid >> 5;

        __shared__ int   s_idx[NN];
        __shared__ float s_val[NN];
        __shared__ int   s_wcnt[8];
        __shared__ int   s_woff[8];
        __shared__ int   s_cnt;
        __shared__ float s_red[8 * DNF];

        const float* arow = adj + (size_t)i * NN;
        const int base = w * 128;

        float av[4]; unsigned mm[4];
#pragma unroll
        for (int c = 0; c < 4; c++) av[c] = arow[base + c * 32 + lane];
        int tot = 0;
#pragma unroll
        for (int c = 0; c < 4; c++) {
            mm[c] = __ballot_sync(0xffffffffu, av[c] != 0.0f);
            tot += __popc(mm[c]);
        }
        if (lane == 0) s_wcnt[w] = tot;
        __syncthreads();
        if (tid == 0) {
            int run = 0;
            for (int ww = 0; ww < 8; ww++) { s_woff[ww] = run; run += s_wcnt[ww]; }
            s_cnt = run;
        }
        __syncthreads();

        int off = s_woff[w];
        const unsigned lm = (1u << lane) - 1u;
#pragma unroll
        for (int c = 0; c < 4; c++) {
            if (av[c] != 0.0f) {
                int p = off + __popc(mm[c] & lm);
                s_idx[p] = base + c * 32 + lane;
                s_val[p] = av[c];
            }
            off += __popc(mm[c]);
        }
        __syncthreads();

        const int cnt = s_cnt;
        if (tid == 0) g_nzc[i] = cnt;
        for (int k = tid; k < cnt; k += 256) {
            g_nzi[(size_t)i * NN + k] = s_idx[k];
            g_nzv[(size_t)i * NN + k] = s_val[k];
        }

        const int q = tid & 31;
        const int g = tid >> 5;
        const float* ebase = e + (size_t)i * NN * DNF;
        float4 acc = make_float4(0.f, 0.f, 0.f, 0.f);
        for (int k = g; k < cnt; k += 8) {
            float v = s_val[k];
            float4 ev = *(const float4*)(ebase + (size_t)s_idx[k] * DNF + q * 4);
            acc.x += v * ev.x; acc.y += v * ev.y;
            acc.z += v * ev.z; acc.w += v * ev.w;
        }
        s_red[g * DNF + q * 4 + 0] = acc.x;
        s_red[g * DNF + q * 4 + 1] = acc.y;
        s_red[g * DNF + q * 4 + 2] = acc.z;
        s_red[g * DNF + q * 4 + 3] = acc.w;
        __syncthreads();
        if (tid < 128) {
            float s = 0.f;
#pragma unroll
            for (int gg = 0; gg < 8; gg++) s += s_red[gg * DNF + tid];
            g_er[(size_t)i * DNF + tid] = s;
        }
        return;
    }

    const int sid = bid - NN;
    if (sid < 384) {
        // wim / wie: elem (n, k) of w_ih @ w_msg_{h,e}  -> packed tf32
        const bool is_h = (sid < 192);
        const int  lsid = is_h ? sid : sid - 192;
        const float* B = is_h ? w_msg_h : w_msg_e;
        float* P = is_h ? g_wimP : g_wieP;
        int id = lsid * 256 + tid;           // 0..49151
        int n = id >> 7, k = id & 127;
        float acc = 0.f;
        const float* wr = w_ih + (size_t)n * DNF;
#pragma unroll 4
        for (int d = 0; d < DNF; d++) acc += wr[d] * B[(size_t)d * DNF + k];
        P[pidx(n, k, 48)] = to_tf32(acc);
    } else if (sid < 432) {
        // pack w_hh (N=384, K=128)
        int b = sid - 384;                    // 0..47
#pragma unroll
        for (int rep = 0; rep < 4; rep++) {
            int eid = b * 1024 + rep * 256 + tid;
            int n = eid >> 7, k = eid & 127;
            g_whhP[pidx(n, k, 48)] = to_tf32(w_hh[(size_t)n * DNF + k]);
        }
    } else if (sid < 464) {
        // pack w_gate (N=128, K=256)
        int b = sid - 432;
#pragma unroll
        for (int rep = 0; rep < 4; rep++) {
            int eid = b * 1024 + rep * 256 + tid;
            int n = eid >> 8, k = eid & 255;
            g_wgP[pidx(n, k, 16)] = to_tf32(w_gate[(size_t)n * 256 + k]);
        }
    } else if (sid < 496) {
        // pack w_out (N=128, K=256)
        int b = sid - 464;
#pragma unroll
        for (int rep = 0; rep < 4; rep++) {
            int eid = b * 1024 + rep * 256 + tid;
            int n = eid >> 8, k = eid & 255;
            g_woP[pidx(n, k, 16)] = to_tf32(w_out[(size_t)n * 256 + k]);
        }
    } else {
        // bvec = w_ih @ b_msg
        for (int n = tid; n < G3; n += 256) {
            float acc = 0.f;
            const float* wr = w_ih + (size_t)n * DNF;
            for (int k = 0; k < DNF; k++) acc += wr[k] * b_msg[k];
            g_bvec[n] = acc;
        }
    }
}

// ---------------------------------------------------------------------------
// k_cei: cei[r0..+16][0..384) = er @ wie^T + bvec.  64 blocks x 512 threads.
// ---------------------------------------------------------------------------
__global__ void __launch_bounds__(512)
k_cei() {
    __shared__ float sA[16 * SLD];
    const int tid  = threadIdx.x;
    const int lane = tid & 31;
    const int wn   = tid >> 5;        // 16 warps, warp = 3 n8 frags
    const int q    = lane >> 2, r = lane & 3;
    const int r0   = blockIdx.x * 16;

    // stage er tile (tf32)
#pragma unroll
    for (int rep = 0; rep < 4; rep++) {
        int eid = tid + rep * 512;
        int i = eid >> 7, d = eid & 127;
        sA[i * SLD + d] = to_tf32(g_er[(size_t)(r0 + i) * DNF + d]);
    }
    __syncthreads();

    float acc[3][4];
#pragma unroll
    for (int j = 0; j < 3; j++)
#pragma unroll
        for (int c = 0; c < 4; c++) acc[j][c] = 0.f;

    const float2* bp = (const float2*)g_wieP;
#pragma unroll
    for (int k8 = 0; k8 < 16; k8++) {
        int ko = k8 * 8;
        unsigned a[4];
        a[0] = __float_as_uint(sA[q * SLD + ko + r]);
        a[1] = __float_as_uint(sA[(q + 8) * SLD + ko + r]);
        a[2] = __float_as_uint(sA[q * SLD + ko + r + 4]);
        a[3] = __float_as_uint(sA[(q + 8) * SLD + ko + r + 4]);
#pragma unroll
        for (int j = 0; j < 3; j++) {
            float2 bb = bp[(k8 * 48 + wn * 3 + j) * 32 + lane];
            mma_tf32(acc[j], a, __float_as_uint(bb.x), __float_as_uint(bb.y));
        }
    }

#pragma unroll
    for (int j = 0; j < 3; j++) {
        int col = (wn * 3 + j) * 8 + 2 * r;
        float bv0 = g_bvec[col], bv1 = g_bvec[col + 1];
        *(float2*)(g_cei + (size_t)(r0 + q) * G3 + col) =
            make_float2(acc[j][0] + bv0, acc[j][1] + bv1);
        *(float2*)(g_cei + (size_t)(r0 + q + 8) * G3 + col) =
            make_float2(acc[j][2] + bv0, acc[j][3] + bv1);
    }
}

// ---------------------------------------------------------------------------
// k_layer: fused spmv + (gi, gh) TF32 GEMMs + GRU for 16 rows per block.
// 64 blocks x 512 threads.  A-tile smem is reused for n-gate storage after
// the MMA loop (alias, separated by __syncthreads).
// ---------------------------------------------------------------------------
__global__ void __launch_bounds__(512)
k_layer(const float* __restrict__ hprev, float* __restrict__ hnext,
        const float* __restrict__ b_ih, const float* __restrict__ b_hh) {
    __shared__ float sAbuf[2 * 16 * SLD];   // sh_t | hh_t ; later gbi | gbh
    __shared__ float ga[16 * GA_LD];        // combined r,z pre-activations

    float* sh_t = sAbuf;
    float* hh_t = sAbuf + 16 * SLD;
    float* gbi  = sAbuf;                    // alias (valid after sync)
    float* gbh  = sAbuf + 16 * SLD;

    const int tid  = threadIdx.x;
    const int lane = tid & 31;
    const int w    = tid >> 5;              // 16 warps
    const int q    = lane >> 2, r = lane & 3;
    const int r0   = blockIdx.x * 16;

    // ---- spmv: row per warp; also stage h tile ----
    {
        const int row = r0 + w;
        const int cnt = g_nzc[row];
        const int*   gip = g_nzi + (size_t)row * NN;
        const float* gvp = g_nzv + (size_t)row * NN;
        float4 acc = warp_gather(hprev, gip, gvp, cnt, lane);
        float* d = sh_t + w * SLD + lane * 4;
        d[0] = to_tf32(acc.x); d[1] = to_tf32(acc.y);
        d[2] = to_tf32(acc.z); d[3] = to_tf32(acc.w);
        float4 hv = *(const float4*)(hprev + (size_t)row * DNF + lane * 4);
        float* dh = hh_t + w * SLD + lane * 4;
        dh[0] = to_tf32(hv.x); dh[1] = to_tf32(hv.y);
        dh[2] = to_tf32(hv.z); dh[3] = to_tf32(hv.w);
    }
    __syncthreads();

    // ---- dual MMA: gi (sh @ wim^T), gh (h @ whh^T); warp covers 3 n8 frags
    float acc_i[3][4], acc_h[3][4];
#pragma unroll
    for (int j = 0; j < 3; j++)
#pragma unroll
        for (int c = 0; c < 4; c++) { acc_i[j][c] = 0.f; acc_h[j][c] = 0.f; }

    const float2* bpi = (const float2*)g_wimP;
    const float2* bph = (const float2*)g_whhP;

#pragma unroll
    for (int k8 = 0; k8 < 16; k8++) {
        const int ko = k8 * 8;
        unsigned ai[4], ah[4];
        ai[0] = __float_as_uint(sh_t[q * SLD + ko + r]);
        ai[1] = __float_as_uint(sh_t[(q + 8) * SLD + ko + r]);
        ai[2] = __float_as_uint(sh_t[q * SLD + ko + r + 4]);
        ai[3] = __float_as_uint(sh_t[(q + 8) * SLD + ko + r + 4]);
        ah[0] = __float_as_uint(hh_t[q * SLD + ko + r]);
        ah[1] = __float_as_uint(hh_t[(q + 8) * SLD + ko + r]);
        ah[2] = __float_as_uint(hh_t[q * SLD + ko + r + 4]);
        ah[3] = __float_as_uint(hh_t[(q + 8) * SLD + ko + r + 4]);
#pragma unroll
        for (int j = 0; j < 3; j++) {
            float2 bi = bpi[(k8 * 48 + w * 3 + j) * 32 + lane];
            float2 bh = bph[(k8 * 48 + w * 3 + j) * 32 + lane];
            mma_tf32(acc_i[j], ai, __float_as_uint(bi.x), __float_as_uint(bi.y));
            mma_tf32(acc_h[j], ah, __float_as_uint(bh.x), __float_as_uint(bh.y));
        }
    }
    __syncthreads();   // A-tiles dead; safe to reuse as gbi/gbh

    // ---- epilogue: add cei + biases, stash pre-activations in smem ----
#pragma unroll
    for (int j = 0; j < 3; j++) {
        int col = (w * 3 + j) * 8 + 2 * r;
        float bi0 = b_ih[col], bi1 = b_ih[col + 1];
        float bh0 = b_hh[col], bh1 = b_hh[col + 1];
#pragma unroll
        for (int s = 0; s < 2; s++) {
            int i = q + s * 8;
            int row = r0 + i;
            float gi0 = acc_i[j][s * 2 + 0] + g_cei[(size_t)row * G3 + col]     + bi0;
            float gi1 = acc_i[j][s * 2 + 1] + g_cei[(size_t)row * G3 + col + 1] + bi1;
            float gh0 = acc_h[j][s * 2 + 0] + bh0;
            float gh1 = acc_h[j][s * 2 + 1] + bh1;
            if (col < 256) {
                ga[i * GA_LD + col]     = gi0 + gh0;
                ga[i * GA_LD + col + 1] = gi1 + gh1;
            } else {
                int cc = col - 256;
                gbi[i * GB_LD + cc]     = gi0;
                gbi[i * GB_LD + cc + 1] = gi1;
                gbh[i * GB_LD + cc]     = gh0;
                gbh[i * GB_LD + cc + 1] = gh1;
            }
        }
    }
    __syncthreads();

    // ---- GRU ----
#pragma unroll
    for (int rep = 0; rep < 4; rep++) {
        int eid = tid + rep * 512;             // 16*128
        int i = eid >> 7, d = eid & 127;
        int row = r0 + i;
        float rr = sigf(ga[i * GA_LD + d]);
        float zz = sigf(ga[i * GA_LD + 128 + d]);
        float nn = tanhf(gbi[i * GB_LD + d] + rr * gbh[i * GB_LD + d]);
        float hold = hprev[(size_t)row * DNF + d];
        hnext[(size_t)row * DNF + d] = (1.0f - zz) * nn + zz * hold;
    }
}

// ---------------------------------------------------------------------------
// k_readout: gate/out GEMMs (K=256 over [h_fin | h0]) + sig*tanh + partial
// reduce; last block does the final fc.  64 blocks x 512 threads.
// A-tiles aliased with gate-pre storage (sync-separated).
// ---------------------------------------------------------------------------
__global__ void __launch_bounds__(512)
k_readout(const float* __restrict__ hfin, const float* __restrict__ h0,
          const float* __restrict__ b_gate, const float* __restrict__ b_out,
          const float* __restrict__ w_embed, const float* __restrict__ edge,
          const float* __restrict__ w_fc, const float* __restrict__ b_fc,
          float* __restrict__ out) {
    __shared__ float sAbuf[2 * 16 * SLD];   // sA0 | sA1 ; later gp | op
    __shared__ float sred[512];
    __shared__ float sgv[128], see[128];
    __shared__ int   s_last;

    float* sA0 = sAbuf;
    float* sA1 = sAbuf + 16 * SLD;
    float* gp  = sAbuf;                     // alias (valid after sync)
    float* op  = sAbuf + 16 * SLD;

    const int tid  = threadIdx.x;
    const int lane = tid & 31;
    const int w    = tid >> 5;
    const int q    = lane >> 2, r = lane & 3;
    const int r0   = blockIdx.x * 16;

    // stage both A tiles
    {
        int row = r0 + w;
        float4 v0 = *(const float4*)(hfin + (size_t)row * DNF + lane * 4);
        float4 v1 = *(const float4*)(h0   + (size_t)row * DNF + lane * 4);
        float* d0 = sA0 + w * SLD + lane * 4;
        float* d1 = sA1 + w * SLD + lane * 4;
        d0[0] = to_tf32(v0.x); d0[1] = to_tf32(v0.y);
        d0[2] = to_tf32(v0.z); d0[3] = to_tf32(v0.w);
        d1[0] = to_tf32(v1.x); d1[1] = to_tf32(v1.y);
        d1[2] = to_tf32(v1.z); d1[3] = to_tf32(v1.w);
    }
    __syncthreads();

    // warp mapping: mat = w>>3 (0=gate,1=out), frags n8 = (w&7)*2 + {0,1}
    const int mat = w >> 3;
    const int f0  = (w & 7) * 2;
    const float2* bp = (const float2*)(mat ? g_woP : g_wgP);

    float acc[2][4];
#pragma unroll
    for (int j = 0; j < 2; j++)
#pragma unroll
        for (int c = 0; c < 4; c++) acc[j][c] = 0.f;

#pragma unroll
    for (int k8 = 0; k8 < 32; k8++) {
        const float* At = (k8 < 16) ? sA0 : sA1;
        const int ko = (k8 & 15) * 8;
        unsigned a[4];
        a[0] = __float_as_uint(At[q * SLD + ko + r]);
        a[1] = __float_as_uint(At[(q + 8) * SLD + ko + r]);
        a[2] = __float_as_uint(At[q * SLD + ko + r + 4]);
        a[3] = __float_as_uint(At[(q + 8) * SLD + ko + r + 4]);
#pragma unroll
        for (int j = 0; j < 2; j++) {
            float2 bb = bp[(k8 * 16 + f0 + j) * 32 + lane];
            mma_tf32(acc[j], a, __float_as_uint(bb.x), __float_as_uint(bb.y));
        }
    }
    __syncthreads();   // A-tiles dead; safe to reuse as gp/op

    float* dst = mat ? op : gp;
    const float* bias = mat ? b_out : b_gate;
#pragma unroll
    for (int j = 0; j < 2; j++) {
        int col = (f0 + j) * 8 + 2 * r;
        float b0 = bias[col], b1 = bias[col + 1];
        dst[q * GB_LD + col]           = acc[j][0] + b0;
        dst[q * GB_LD + col + 1]       = acc[j][1] + b1;
        dst[(q + 8) * GB_LD + col]     = acc[j][2] + b0;
        dst[(q + 8) * GB_LD + col + 1] = acc[j][3] + b1;
    }
    __syncthreads();

    // partial: sum over 16 rows of sigmoid(gp)*tanh(op)
    {
        int grp = tid >> 7, d = tid & 127;
        float a = 0.f;
#pragma unroll
        for (int i = grp * 4; i < grp * 4 + 4; i++)
            a += sigf(gp[i * GB_LD + d]) * tanhf(op[i * GB_LD + d]);
        sred[tid] = a;
    }
    __syncthreads();
    if (tid < 128)
        g_part[blockIdx.x * DNF + tid] =
            sred[tid] + sred[tid + 128] + sred[tid + 256] + sred[tid + 384];
    __syncthreads();   // all g_part writes done before signaling

    // last-block final reduction (deterministic order)
    if (tid == 0) {
        __threadfence();
        int old = atomicAdd(&g_rc, 1);
        s_last = (old == 63) ? 1 : 0;
    }
    __syncthreads();
    if (s_last) {
        if (tid == 0) g_rc = 0;
        if (tid < 128) {
            float gv = 0.f;
            for (int b = 0; b < 64; b++) gv += g_part[b * DNF + tid];
            sgv[tid] = gv;
            float ee = 0.f;
#pragma unroll
            for (int f = 0; f < 5; f++) ee += w_embed[tid * 5 + f] * edge[f];
            see[tid] = ee;
        }
        __syncthreads();
        if (tid < 128) {
            float acc2 = b_fc[tid];
            const float* wr = w_fc + (size_t)tid * 256;
            for (int k = 0; k < 128; k++) acc2 += wr[k] * sgv[k];
            for (int k = 0; k < 128; k++) acc2 += wr[128 + k] * see[k];
            out[tid] = acc2;
        }
    }
}

// ---------------------------------------------------------------------------
extern "C" void kernel_launch(void* const* d_in, const int* in_sizes, int n_in,
                              void* d_out, int out_size) {
    const float* h_in    = (const float*)d_in[0];
    const float* e       = (const float*)d_in[1];
    const float* adj     = (const float*)d_in[2];
    const float* edge    = (const float*)d_in[3];
    const float* w_msg_h = (const float*)d_in[4];
    const float* w_msg_e = (const float*)d_in[5];
    const float* b_msg   = (const float*)d_in[6];
    const float* w_ih    = (const float*)d_in[7];
    const float* w_hh    = (const float*)d_in[8];
    const float* b_ih    = (const float*)d_in[9];
    const float* b_hh    = (const float*)d_in[10];
    const float* w_gate  = (const float*)d_in[11];
    const float* b_gate  = (const float*)d_in[12];
    const float* w_out   = (const float*)d_in[13];
    const float* b_out   = (const float*)d_in[14];
    const float* w_embed = (const float*)d_in[15];
    const float* w_fc    = (const float*)d_in[16];
    const float* b_fc    = (const float*)d_in[17];
    float* out = (float*)d_out;

    float *p_ha, *p_hb;
    cudaGetSymbolAddress((void**)&p_ha, g_ha);
    cudaGetSymbolAddress((void**)&p_hb, g_hb);

    // 1) setup: adjacency build + er (1024 blocks) | weight products & packs (497)
    k_setup<<<NN + 497, 256>>>(adj, e, w_msg_h, w_msg_e, w_ih, b_msg,
                               w_hh, w_gate, w_out);
    // 2) cei = er @ wie^T + bvec
    k_cei<<<64, 512>>>();
    // 3-6) fused layers (ping-pong h buffers)
    k_layer<<<64, 512>>>(h_in, p_ha, b_ih, b_hh);
    k_layer<<<64, 512>>>(p_ha, p_hb, b_ih, b_hh);
    k_layer<<<64, 512>>>(p_hb, p_ha, b_ih, b_hh);
    k_layer<<<64, 512>>>(p_ha, p_hb, b_ih, b_hh);
    // 7) readout + final (last-block reduction)
    k_readout<<<64, 512>>>(p_hb, h_in, b_gate, b_out, w_embed, edge,
                           w_fc, b_fc, out);
}

// round 8
// speedup vs baseline: 1.3109x; 1.1686x over previous
#include <cuda_runtime.h>
#include <math.h>

#define NN   1024
#define DNF  128
#define G3   384
#define SLD  132     // A-tile smem stride: 128 k-floats + 4 pad
#define GLD  388     // gate buffer stride: 384 + 4 pad
#define GB_LD 132

// ---------------- device scratch ----------------
__device__ float g_er  [NN * DNF];
__device__ float g_cei [NN * G3];      // er @ wie^T + bvec (layer-invariant)
__device__ float g_ha  [NN * DNF];
__device__ float g_hb  [NN * DNF];
__device__ float g_wimP[16 * 48 * 64]; // packed tf32 frags: (w_ih@w_msg_h), K=128,N=384
__device__ float g_wieP[16 * 48 * 64];
__device__ float g_whhP[16 * 48 * 64];
__device__ float g_wgP [32 * 16 * 64]; // w_gate, K=256, N=128
__device__ float g_woP [32 * 16 * 64];
__device__ float g_bvec[G3];
__device__ int   g_nzi [NN * NN];
__device__ float g_nzv [NN * NN];
__device__ int   g_nzc [NN];
__device__ float g_part[64 * DNF];
__device__ int   g_rc;

// ---------------- helpers ----------------
__device__ __forceinline__ float to_tf32(float x) {
    float r; asm("cvt.rna.tf32.f32 %0, %1;" : "=f"(r) : "f"(x)); return r;
}
__device__ __forceinline__ float sigf(float x) { return 1.0f / (1.0f + expf(-x)); }

__device__ __forceinline__ void mma_tf32(float* c, const unsigned* a,
                                         unsigned b0, unsigned b1) {
    asm volatile(
        "mma.sync.aligned.m16n8k8.row.col.f32.tf32.tf32.f32 "
        "{%0,%1,%2,%3}, {%4,%5,%6,%7}, {%8,%9}, {%0,%1,%2,%3};"
        : "+f"(c[0]), "+f"(c[1]), "+f"(c[2]), "+f"(c[3])
        : "r"(a[0]), "r"(a[1]), "r"(a[2]), "r"(a[3]), "r"(b0), "r"(b1));
}

// packed fragment index for W[N][K] (k-major rows)
__device__ __forceinline__ int pidx(int n, int k, int nfr) {
    int n8 = n >> 3, q = n & 7, k8 = k >> 3, kk = k & 7;
    int half = kk >> 2, r = kk & 3;
    return ((k8 * nfr + n8) * 32 + q * 4 + r) * 2 + half;
}

// nz-list broadcast: first 64 entries register-cached per warp
__device__ __forceinline__ void get_nz(int k, int i0, int i1, float v0, float v1,
                                       const int* gip, const float* gvp,
                                       int& j, float& v) {
    if (k < 32)      { j = __shfl_sync(0xffffffffu, i0, k);      v = __shfl_sync(0xffffffffu, v0, k); }
    else if (k < 64) { j = __shfl_sync(0xffffffffu, i1, k - 32); v = __shfl_sync(0xffffffffu, v1, k - 32); }
    else             { j = gip[k]; v = gvp[k]; }
}

// strided warp gather (stride 2, start = half): partial for one row half
__device__ __forceinline__ float4 warp_gather_half(const float* __restrict__ src,
                                                   const int* gip, const float* gvp,
                                                   int cnt, int lane, int half) {
    int i0 = 0, i1 = 0; float v0 = 0.f, v1 = 0.f;
    if (lane < cnt)      { i0 = gip[lane];      v0 = gvp[lane]; }
    if (32 + lane < cnt) { i1 = gip[32 + lane]; v1 = gvp[32 + lane]; }
    float4 acc = make_float4(0.f, 0.f, 0.f, 0.f);
    int k = half;
    for (; k + 6 < cnt; k += 8) {
        int j0, j1, j2, j3; float w0, w1, w2, w3;
        get_nz(k,     i0, i1, v0, v1, gip, gvp, j0, w0);
        get_nz(k + 2, i0, i1, v0, v1, gip, gvp, j1, w1);
        get_nz(k + 4, i0, i1, v0, v1, gip, gvp, j2, w2);
        get_nz(k + 6, i0, i1, v0, v1, gip, gvp, j3, w3);
        float4 a0 = *(const float4*)(src + (size_t)j0 * DNF + lane * 4);
        float4 a1 = *(const float4*)(src + (size_t)j1 * DNF + lane * 4);
        float4 a2 = *(const float4*)(src + (size_t)j2 * DNF + lane * 4);
        float4 a3 = *(const float4*)(src + (size_t)j3 * DNF + lane * 4);
        acc.x += w0*a0.x + w1*a1.x + w2*a2.x + w3*a3.x;
        acc.y += w0*a0.y + w1*a1.y + w2*a2.y + w3*a3.y;
        acc.z += w0*a0.z + w1*a1.z + w2*a2.z + w3*a3.z;
        acc.w += w0*a0.w + w1*a1.w + w2*a2.w + w3*a3.w;
    }
    for (; k < cnt; k += 2) {
        int j; float w;
        get_nz(k, i0, i1, v0, v1, gip, gvp, j, w);
        float4 av = *(const float4*)(src + (size_t)j * DNF + lane * 4);
        acc.x += w*av.x; acc.y += w*av.y; acc.z += w*av.z; acc.w += w*av.w;
    }
    return acc;
}

// ---------------------------------------------------------------------------
// k_setup: bid<1024 — adjacency compaction + er; bid>=1024 — weight
// products (wim, wie), packing (whh, wgate, wout), bvec.   256 threads.
// ---------------------------------------------------------------------------
__global__ void __launch_bounds__(256)
k_setup(const float* __restrict__ adj, const float* __restrict__ e,
        const float* __restrict__ w_msg_h, const float* __restrict__ w_msg_e,
        const float* __restrict__ w_ih, const float* __restrict__ b_msg,
        const float* __restrict__ w_hh, const float* __restrict__ w_gate,
        const float* __restrict__ w_out) {
    const int bid = blockIdx.x;
    const int tid = threadIdx.x;

    if (bid < NN) {
        const int i    = bid;
        const int lane = tid & 31;
        const int w    = tid >> 5;

        __shared__ int   s_idx[NN];
        __shared__ float s_val[NN];
        __shared__ int   s_wcnt[8];
        __shared__ int   s_woff[8];
        __shared__ int   s_cnt;
        __shared__ float s_red[8 * DNF];

        const float* arow = adj + (size_t)i * NN;
        const int base = w * 128;

        float av[4]; unsigned mm[4];
#pragma unroll
        for (int c = 0; c < 4; c++) av[c] = arow[base + c * 32 + lane];
        int tot = 0;
#pragma unroll
        for (int c = 0; c < 4; c++) {
            mm[c] = __ballot_sync(0xffffffffu, av[c] != 0.0f);
            tot += __popc(mm[c]);
        }
        if (lane == 0) s_wcnt[w] = tot;
        __syncthreads();
        if (tid == 0) {
            int run = 0;
            for (int ww = 0; ww < 8; ww++) { s_woff[ww] = run; run += s_wcnt[ww]; }
            s_cnt = run;
        }
        __syncthreads();

        int off = s_woff[w];
        const unsigned lm = (1u << lane) - 1u;
#pragma unroll
        for (int c = 0; c < 4; c++) {
            if (av[c] != 0.0f) {
                int p = off + __popc(mm[c] & lm);
                s_idx[p] = base + c * 32 + lane;
                s_val[p] = av[c];
            }
            off += __popc(mm[c]);
        }
        __syncthreads();

        const int cnt = s_cnt;
        if (tid == 0) g_nzc[i] = cnt;
        for (int k = tid; k < cnt; k += 256) {
            g_nzi[(size_t)i * NN + k] = s_idx[k];
            g_nzv[(size_t)i * NN + k] = s_val[k];
        }

        const int q = tid & 31;
        const int g = tid >> 5;
        const float* ebase = e + (size_t)i * NN * DNF;
        float4 acc = make_float4(0.f, 0.f, 0.f, 0.f);
        for (int k = g; k < cnt; k += 8) {
            float v = s_val[k];
            float4 ev = *(const float4*)(ebase + (size_t)s_idx[k] * DNF + q * 4);
            acc.x += v * ev.x; acc.y += v * ev.y;
            acc.z += v * ev.z; acc.w += v * ev.w;
        }
        s_red[g * DNF + q * 4 + 0] = acc.x;
        s_red[g * DNF + q * 4 + 1] = acc.y;
        s_red[g * DNF + q * 4 + 2] = acc.z;
        s_red[g * DNF + q * 4 + 3] = acc.w;
        __syncthreads();
        if (tid < 128) {
            float s = 0.f;
#pragma unroll
            for (int gg = 0; gg < 8; gg++) s += s_red[gg * DNF + tid];
            g_er[(size_t)i * DNF + tid] = s;
        }
        return;
    }

    const int sid = bid - NN;
    if (sid < 384) {
        const bool is_h = (sid < 192);
        const int  lsid = is_h ? sid : sid - 192;
        const float* B = is_h ? w_msg_h : w_msg_e;
        float* P = is_h ? g_wimP : g_wieP;
        int id = lsid * 256 + tid;
        int n = id >> 7, k = id & 127;
        float acc = 0.f;
        const float* wr = w_ih + (size_t)n * DNF;
#pragma unroll 4
        for (int d = 0; d < DNF; d++) acc += wr[d] * B[(size_t)d * DNF + k];
        P[pidx(n, k, 48)] = to_tf32(acc);
    } else if (sid < 432) {
        int b = sid - 384;
#pragma unroll
        for (int rep = 0; rep < 4; rep++) {
            int eid = b * 1024 + rep * 256 + tid;
            int n = eid >> 7, k = eid & 127;
            g_whhP[pidx(n, k, 48)] = to_tf32(w_hh[(size_t)n * DNF + k]);
        }
    } else if (sid < 464) {
        int b = sid - 432;
#pragma unroll
        for (int rep = 0; rep < 4; rep++) {
            int eid = b * 1024 + rep * 256 + tid;
            int n = eid >> 8, k = eid & 255;
            g_wgP[pidx(n, k, 16)] = to_tf32(w_gate[(size_t)n * 256 + k]);
        }
    } else if (sid < 496) {
        int b = sid - 464;
#pragma unroll
        for (int rep = 0; rep < 4; rep++) {
            int eid = b * 1024 + rep * 256 + tid;
            int n = eid >> 8, k = eid & 255;
            g_woP[pidx(n, k, 16)] = to_tf32(w_out[(size_t)n * 256 + k]);
        }
    } else {
        for (int n = tid; n < G3; n += 256) {
            float acc = 0.f;
            const float* wr = w_ih + (size_t)n * DNF;
            for (int k = 0; k < DNF; k++) acc += wr[k] * b_msg[k];
            g_bvec[n] = acc;
        }
    }
}

// ---------------------------------------------------------------------------
// k_cei: cei = er @ wie^T + bvec.  64 blocks x 1024 threads.
// 32 warps = 16 n-warps x 2 k-halves; split-K reduced via padded smem.
// ---------------------------------------------------------------------------
__global__ void __launch_bounds__(1024)
k_cei() {
    __shared__ float sA[16 * SLD];
    __shared__ float red[16 * 32 * 13];

    const int tid  = threadIdx.x;
    const int lane = tid & 31;
    const int w    = tid >> 5;        // 32 warps
    const int nw   = w & 15;
    const int kh   = w >> 4;
    const int q    = lane >> 2, r = lane & 3;
    const int r0   = blockIdx.x * 16;

#pragma unroll
    for (int rep = 0; rep < 2; rep++) {
        int eid = tid + rep * 1024;
        int i = eid >> 7, d = eid & 127;
        sA[i * SLD + d] = to_tf32(g_er[(size_t)(r0 + i) * DNF + d]);
    }
    __syncthreads();

    float acc[3][4];
#pragma unroll
    for (int j = 0; j < 3; j++)
#pragma unroll
        for (int c = 0; c < 4; c++) acc[j][c] = 0.f;

    const float2* bp = (const float2*)g_wieP;

    float2 bf[2][3];
#pragma unroll
    for (int j = 0; j < 3; j++)
        bf[0][j] = bp[((kh * 8) * 48 + nw * 3 + j) * 32 + lane];

#pragma unroll
    for (int kk = 0; kk < 8; kk++) {
        const int k8 = kh * 8 + kk;
        const int cur = kk & 1, nxt = cur ^ 1;
        if (kk < 7) {
#pragma unroll
            for (int j = 0; j < 3; j++)
                bf[nxt][j] = bp[((k8 + 1) * 48 + nw * 3 + j) * 32 + lane];
        }
        const int ko = k8 * 8;
        unsigned a[4];
        a[0] = __float_as_uint(sA[q * SLD + ko + r]);
        a[1] = __float_as_uint(sA[(q + 8) * SLD + ko + r]);
        a[2] = __float_as_uint(sA[q * SLD + ko + r + 4]);
        a[3] = __float_as_uint(sA[(q + 8) * SLD + ko + r + 4]);
#pragma unroll
        for (int j = 0; j < 3; j++)
            mma_tf32(acc[j], a, __float_as_uint(bf[cur][j].x),
                               __float_as_uint(bf[cur][j].y));
    }

    if (kh == 1) {
        float* rp = red + (nw * 32 + lane) * 13;
#pragma unroll
        for (int j = 0; j < 3; j++)
#pragma unroll
            for (int c = 0; c < 4; c++) rp[j * 4 + c] = acc[j][c];
    }
    __syncthreads();
    if (kh == 0) {
        const float* rp = red + (nw * 32 + lane) * 13;
#pragma unroll
        for (int j = 0; j < 3; j++) {
#pragma unroll
            for (int c = 0; c < 4; c++) acc[j][c] += rp[j * 4 + c];
            int col = (nw * 3 + j) * 8 + 2 * r;
            float bv0 = g_bvec[col], bv1 = g_bvec[col + 1];
            *(float2*)(g_cei + (size_t)(r0 + q) * G3 + col) =
                make_float2(acc[j][0] + bv0, acc[j][1] + bv1);
            *(float2*)(g_cei + (size_t)(r0 + q + 8) * G3 + col) =
                make_float2(acc[j][2] + bv0, acc[j][3] + bv1);
        }
    }
}

// ---------------------------------------------------------------------------
// k_layer: fused spmv + dual TF32 GEMM + GRU for 16 rows. 64 blocks x 1024 thr.
// 32 warps = 2 matrices x 16 n-warps.
// ---------------------------------------------------------------------------
__global__ void __launch_bounds__(1024)
k_layer(const float* __restrict__ hprev, float* __restrict__ hnext,
        const float* __restrict__ b_ih, const float* __restrict__ b_hh) {
    __shared__ float sAbuf[2 * 16 * SLD];   // sh_t | hh_t ; sh_t later = gbi
    __shared__ float G[16 * GLD];           // first used as ph[32][32] float4

    float*  sh_t = sAbuf;
    float*  hh_t = sAbuf + 16 * SLD;
    float*  gbi  = sAbuf;                   // alias (valid after MMA sync)
    float4* ph   = (float4*)G;

    const int tid  = threadIdx.x;
    const int lane = tid & 31;
    const int w    = tid >> 5;              // 32 warps
    const int q    = lane >> 2, r = lane & 3;
    const int r0   = blockIdx.x * 16;

    // ---- phase 1a: strided gather halves (2 warps per row) ----
    {
        const int row  = r0 + (w & 15);
        const int half = w >> 4;
        const int cnt  = g_nzc[row];
        const int*   gip = g_nzi + (size_t)row * NN;
        const float* gvp = g_nzv + (size_t)row * NN;
        ph[w * 32 + lane] = warp_gather_half(hprev, gip, gvp, cnt, lane, half);
    }
    __syncthreads();

    // ---- phase 1b: combine halves -> sh_t ; stage h -> hh_t ----
    if (w < 16) {
        float4 a = ph[w * 32 + lane];
        float4 b = ph[(w + 16) * 32 + lane];
        float* d = sh_t + w * SLD + lane * 4;
        d[0] = to_tf32(a.x + b.x); d[1] = to_tf32(a.y + b.y);
        d[2] = to_tf32(a.z + b.z); d[3] = to_tf32(a.w + b.w);
    } else {
        int row = r0 + (w - 16);
        float4 hv = *(const float4*)(hprev + (size_t)row * DNF + lane * 4);
        float* dh = hh_t + (w - 16) * SLD + lane * 4;
        dh[0] = to_tf32(hv.x); dh[1] = to_tf32(hv.y);
        dh[2] = to_tf32(hv.z); dh[3] = to_tf32(hv.w);
    }
    __syncthreads();

    // ---- phase 2: MMA (mat 0: gi = sh@wim^T ; mat 1: gh = h@whh^T) ----
    const int mat = w >> 4;
    const int nw  = w & 15;
    const float*  At = mat ? hh_t : sh_t;
    const float2* bp = (const float2*)(mat ? g_whhP : g_wimP);

    float acc[3][4];
#pragma unroll
    for (int j = 0; j < 3; j++)
#pragma unroll
        for (int c = 0; c < 4; c++) acc[j][c] = 0.f;

    float2 bf[2][3];
#pragma unroll
    for (int j = 0; j < 3; j++)
        bf[0][j] = bp[(0 * 48 + nw * 3 + j) * 32 + lane];

#pragma unroll
    for (int k8 = 0; k8 < 16; k8++) {
        const int cur = k8 & 1, nxt = cur ^ 1;
        if (k8 < 15) {
#pragma unroll
            for (int j = 0; j < 3; j++)
                bf[nxt][j] = bp[((k8 + 1) * 48 + nw * 3 + j) * 32 + lane];
        }
        const int ko = k8 * 8;
        unsigned a[4];
        a[0] = __float_as_uint(At[q * SLD + ko + r]);
        a[1] = __float_as_uint(At[(q + 8) * SLD + ko + r]);
        a[2] = __float_as_uint(At[q * SLD + ko + r + 4]);
        a[3] = __float_as_uint(At[(q + 8) * SLD + ko + r + 4]);
#pragma unroll
        for (int j = 0; j < 3; j++)
            mma_tf32(acc[j], a, __float_as_uint(bf[cur][j].x),
                               __float_as_uint(bf[cur][j].y));
    }

    // gh warps: write gh + b_hh into G (ph already consumed)
    if (mat == 1) {
#pragma unroll
        for (int j = 0; j < 3; j++) {
            int col = (nw * 3 + j) * 8 + 2 * r;
            float b0 = b_hh[col], b1 = b_hh[col + 1];
            G[q * GLD + col]           = acc[j][0] + b0;
            G[q * GLD + col + 1]       = acc[j][1] + b1;
            G[(q + 8) * GLD + col]     = acc[j][2] + b0;
            G[(q + 8) * GLD + col + 1] = acc[j][3] + b1;
        }
    }
    __syncthreads();

    // gi warps: combine with cei + b_ih
    if (mat == 0) {
#pragma unroll
        for (int j = 0; j < 3; j++) {
            int col = (nw * 3 + j) * 8 + 2 * r;
            float bi0 = b_ih[col], bi1 = b_ih[col + 1];
#pragma unroll
            for (int s = 0; s < 2; s++) {
                int i = q + s * 8;
                int row = r0 + i;
                float2 ce = *(const float2*)(g_cei + (size_t)row * G3 + col);
                float gi0 = acc[j][s * 2 + 0] + ce.x + bi0;
                float gi1 = acc[j][s * 2 + 1] + ce.y + bi1;
                if (col < 256) {
                    G[i * GLD + col]     += gi0;
                    G[i * GLD + col + 1] += gi1;
                } else {
                    gbi[i * GB_LD + (col - 256)]     = gi0;
                    gbi[i * GB_LD + (col - 256) + 1] = gi1;
                }
            }
        }
    }
    __syncthreads();

    // ---- GRU ----
#pragma unroll
    for (int rep = 0; rep < 2; rep++) {
        int eid = tid + rep * 1024;             // 16*128
        int i = eid >> 7, d = eid & 127;
        int row = r0 + i;
        float rr = sigf(G[i * GLD + d]);
        float zz = sigf(G[i * GLD + 128 + d]);
        float nn = tanhf(gbi[i * GB_LD + d] + rr * G[i * GLD + 256 + d]);
        float hold = hprev[(size_t)row * DNF + d];
        hnext[(size_t)row * DNF + d] = (1.0f - zz) * nn + zz * hold;
    }
}

// ---------------------------------------------------------------------------
// k_readout: gate/out GEMMs (K=256) + sig*tanh + partial reduce + final fc.
// 64 blocks x 1024 threads. 32 warps = 2 mats x 2 k-halves x 8 frag-groups.
// ---------------------------------------------------------------------------
__global__ void __launch_bounds__(1024)
k_readout(const float* __restrict__ hfin, const float* __restrict__ h0,
          const float* __restrict__ b_gate, const float* __restrict__ b_out,
          const float* __restrict__ w_embed, const float* __restrict__ edge,
          const float* __restrict__ w_fc, const float* __restrict__ b_fc,
          float* __restrict__ out) {
    __shared__ float sAbuf[2 * 16 * SLD];   // sA0 | sA1 ; later gp | op
    __shared__ float red[16 * 32 * 9];
    __shared__ float sred[1024];
    __shared__ float sgv[128], see[128];
    __shared__ int   s_last;

    float* sA0 = sAbuf;
    float* sA1 = sAbuf + 16 * SLD;
    float* gp  = sAbuf;                     // alias (valid after MMA sync)
    float* op  = sAbuf + 16 * SLD;

    const int tid  = threadIdx.x;
    const int lane = tid & 31;
    const int w    = tid >> 5;              // 32 warps
    const int fg   = w & 7;
    const int mat  = (w >> 3) & 1;
    const int kh   = w >> 4;
    const int q    = lane >> 2, r = lane & 3;
    const int r0   = blockIdx.x * 16;

    // stage A tiles: warps 0-15 -> sA0 (hfin), 16-31 -> sA1 (h0)
    {
        const float* src = (w < 16) ? hfin : h0;
        float* dst = (w < 16) ? sA0 : sA1;
        int row = r0 + (w & 15);
        float4 v = *(const float4*)(src + (size_t)row * DNF + lane * 4);
        float* d = dst + (w & 15) * SLD + lane * 4;
        d[0] = to_tf32(v.x); d[1] = to_tf32(v.y);
        d[2] = to_tf32(v.z); d[3] = to_tf32(v.w);
    }
    __syncthreads();

    const float2* bp = (const float2*)(mat ? g_woP : g_wgP);
    const float* At = kh ? sA1 : sA0;

    float acc[2][4];
#pragma unroll
    for (int j = 0; j < 2; j++)
#pragma unroll
        for (int c = 0; c < 4; c++) acc[j][c] = 0.f;

    float2 bf[2][2];
#pragma unroll
    for (int j = 0; j < 2; j++)
        bf[0][j] = bp[((kh * 16) * 16 + fg * 2 + j) * 32 + lane];

#pragma unroll
    for (int kk = 0; kk < 16; kk++) {
        const int k8 = kh * 16 + kk;
        const int cur = kk & 1, nxt = cur ^ 1;
        if (kk < 15) {
#pragma unroll
            for (int j = 0; j < 2; j++)
                bf[nxt][j] = bp[((k8 + 1) * 16 + fg * 2 + j) * 32 + lane];
        }
        const int ko = kk * 8;
        unsigned a[4];
        a[0] = __float_as_uint(At[q * SLD + ko + r]);
        a[1] = __float_as_uint(At[(q + 8) * SLD + ko + r]);
        a[2] = __float_as_uint(At[q * SLD + ko + r + 4]);
        a[3] = __float_as_uint(At[(q + 8) * SLD + ko + r + 4]);
#pragma unroll
        for (int j = 0; j < 2; j++)
            mma_tf32(acc[j], a, __float_as_uint(bf[cur][j].x),
                               __float_as_uint(bf[cur][j].y));
    }

    if (kh == 1) {
        float* rp = red + ((mat * 8 + fg) * 32 + lane) * 9;
#pragma unroll
        for (int j = 0; j < 2; j++)
#pragma unroll
            for (int c = 0; c < 4; c++) rp[j * 4 + c] = acc[j][c];
    }
    __syncthreads();
    if (kh == 0) {
        const float* rp = red + ((mat * 8 + fg) * 32 + lane) * 9;
        float* dst = mat ? op : gp;
        const float* bias = mat ? b_out : b_gate;
#pragma unroll
        for (int j = 0; j < 2; j++) {
#pragma unroll
            for (int c = 0; c < 4; c++) acc[j][c] += rp[j * 4 + c];
            int col = (fg * 2 + j) * 8 + 2 * r;
            float b0 = bias[col], b1 = bias[col + 1];
            dst[q * GB_LD + col]           = acc[j][0] + b0;
            dst[q * GB_LD + col + 1]       = acc[j][1] + b1;
            dst[(q + 8) * GB_LD + col]     = acc[j][2] + b0;
            dst[(q + 8) * GB_LD + col + 1] = acc[j][3] + b1;
        }
    }
    __syncthreads();

    // partial: sum over 16 rows of sigmoid(gp)*tanh(op)
    {
        int grp = tid >> 7, d = tid & 127;
        float a = 0.f;
#pragma unroll
        for (int i = grp * 2; i < grp * 2 + 2; i++)
            a += sigf(gp[i * GB_LD + d]) * tanhf(op[i * GB_LD + d]);
        sred[tid] = a;
    }
    __syncthreads();
    if (tid < 128) {
        float s = 0.f;
#pragma unroll
        for (int g = 0; g < 8; g++) s += sred[g * 128 + tid];
        g_part[blockIdx.x * DNF + tid] = s;
    }
    __syncthreads();

    if (tid == 0) {
        __threadfence();
        int old = atomicAdd(&g_rc, 1);
        s_last = (old == 63) ? 1 : 0;
    }
    __syncthreads();
    if (s_last) {
        if (tid == 0) g_rc = 0;
        if (tid < 128) {
            float gv = 0.f;
            for (int b = 0; b < 64; b++) gv += g_part[b * DNF + tid];
            sgv[tid] = gv;
            float ee = 0.f;
#pragma unroll
            for (int f = 0; f < 5; f++) ee += w_embed[tid * 5 + f] * edge[f];
            see[tid] = ee;
        }
        __syncthreads();
        if (tid < 128) {
            float acc2 = b_fc[tid];
            const float* wr = w_fc + (size_t)tid * 256;
            for (int k = 0; k < 128; k++) acc2 += wr[k] * sgv[k];
            for (int k = 0; k < 128; k++) acc2 += wr[128 + k] * see[k];
            out[tid] = acc2;
        }
    }
}

// ---------------------------------------------------------------------------
extern "C" void kernel_launch(void* const* d_in, const int* in_sizes, int n_in,
                              void* d_out, int out_size) {
    const float* h_in    = (const float*)d_in[0];
    const float* e       = (const float*)d_in[1];
    const float* adj     = (const float*)d_in[2];
    const float* edge    = (const float*)d_in[3];
    const float* w_msg_h = (const float*)d_in[4];
    const float* w_msg_e = (const float*)d_in[5];
    const float* b_msg   = (const float*)d_in[6];
    const float* w_ih    = (const float*)d_in[7];
    const float* w_hh    = (const float*)d_in[8];
    const float* b_ih    = (const float*)d_in[9];
    const float* b_hh    = (const float*)d_in[10];
    const float* w_gate  = (const float*)d_in[11];
    const float* b_gate  = (const float*)d_in[12];
    const float* w_out   = (const float*)d_in[13];
    const float* b_out   = (const float*)d_in[14];
    const float* w_embed = (const float*)d_in[15];
    const float* w_fc    = (const float*)d_in[16];
    const float* b_fc    = (const float*)d_in[17];
    float* out = (float*)d_out;

    float *p_ha, *p_hb;
    cudaGetSymbolAddress((void**)&p_ha, g_ha);
    cudaGetSymbolAddress((void**)&p_hb, g_hb);

    k_setup<<<NN + 497, 256>>>(adj, e, w_msg_h, w_msg_e, w_ih, b_msg,
                               w_hh, w_gate, w_out);
    k_cei<<<64, 1024>>>();
    k_layer<<<64, 1024>>>(h_in, p_ha, b_ih, b_hh);
    k_layer<<<64, 1024>>>(p_ha, p_hb, b_ih, b_hh);
    k_layer<<<64, 1024>>>(p_hb, p_ha, b_ih, b_hh);
    k_layer<<<64, 1024>>>(p_ha, p_hb, b_ih, b_hh);
    k_readout<<<64, 1024>>>(p_hb, h_in, b_gate, b_out, w_embed, edge,
                            w_fc, b_fc, out);
}